// round 8
// baseline (speedup 1.0000x reference)
#include <cuda_runtime.h>
#include <math.h>

#define Hh 128
#define Ww 128
#define Nn (Hh*Ww)      // 16384
#define Cc 64
#define TT 64           // tokens per tile
#define TILES (Nn/TT)   // 256
#define PB 64           // k_pass blocks per batch
#define BMAX 16

// Deterministic scratch
__device__ float g_part_kv[BMAX*PB*1024];
__device__ float g_part_ks[BMAX*PB*64];
__device__ float g_kvn[BMAX*1024];
__device__ float g_kmean[BMAX*64];
__device__ float2 g_cs[2048];   // [pos 0..127][k 0..15] -> (cos, sin)

#define LN1E4_OVER16 0.57564627324851145f

__device__ __forceinline__ float elu1(float v) { return v > 0.f ? v + 1.f : __expf(v); }

__device__ __forceinline__ unsigned long long pack2(float lo, float hi) {
    unsigned long long r;
    asm("mov.b64 %0, {%1,%2};" : "=l"(r) : "f"(lo), "f"(hi));
    return r;
}
__device__ __forceinline__ float2 unpack2(unsigned long long v) {
    float2 r;
    asm("mov.b64 {%0,%1}, %2;" : "=f"(r.x), "=f"(r.y) : "l"(v));
    return r;
}
__device__ __forceinline__ void fma2(unsigned long long& d, unsigned long long a, unsigned long long b) {
    asm("fma.rn.f32x2 %0, %1, %2, %0;" : "+l"(d) : "l"(a), "l"(b));
}

// ---------------------------------------------------------------------------
__global__ void init_tables() {
    int idx = threadIdx.x + blockIdx.x * 256;
    if (idx < 2048) {
        int pos = idx >> 4, k = idx & 15;
        float theta = expf(-(float)k * LN1E4_OVER16);
        float ang = (float)pos * theta;
        g_cs[idx] = make_float2(cosf(ang), sinf(ang));
    }
}

// ---------------------------------------------------------------------------
// k_pass smem (floats): Wi 4096 | xs 64x68 | ks 64x68   (51200 B)
// ---------------------------------------------------------------------------
__global__ __launch_bounds__(256, 4) void k_pass(const float* __restrict__ x,
                                                 const float* __restrict__ qkw,
                                                 const float* __restrict__ qkb) {
    extern __shared__ float sm[];
    float4* sWi4 = (float4*)sm;
    const ulonglong2* sW2 = (const ulonglong2*)sm;
    float (*xs)[68] = (float (*)[68])(sm + 4096);
    float (*ks)[68] = (float (*)[68])(sm + 8448);

    const int b  = blockIdx.y;
    const int pb = blockIdx.x;
    const int tid = threadIdx.x;

    // W interleaved-granule layout: [c4*64 + (f&3)*16 + (f>>2)] = W[f][c4*4..+3]
    for (int i = tid; i < 1024; i += 256) {
        int f = i >> 4, c4 = i & 15;
        float4 v = *(const float4*)(qkw + (size_t)(64 + f) * 64 + c4 * 4);
        sWi4[c4 * 64 + (f & 3) * 16 + (f >> 2)] = v;
    }

    const int ff = tid & 15;
    const int tt = tid >> 4;
    const int f0 = ff * 4;
    const int tb = tt * 4;

    const int kid0 = (2 * ff) & 15, kid1 = (2 * ff + 1) & 15;
    const bool useH = (ff < 8);

    const float4 bias4 = *(const float4*)(qkb + 64 + f0);

    float ksum[4] = {0.f, 0.f, 0.f, 0.f};

    // kv accumulate ownership: 4x4 (d,e) block, 4-way t-split
    const int e4 = (tid & 3) * 4;
    const int d4 = ((tid >> 2) & 3) * 4;
    const int q4 = (tid >> 4) & 3;
    const int hd2 = tid >> 6;
    unsigned long long kvp[4][2] = {};   // [dj][e-pair]

    const float* xb = x + (size_t)b * Nn * Cc;

    for (int tile = pb; tile < TILES; tile += PB) {
        const int token0 = tile * TT;
        __syncthreads();

        for (int i = tid; i < TT * 16; i += 256) {
            int t = i >> 4, c4 = i & 15;
            float4 v = *(const float4*)(xb + (size_t)(token0 + t) * Cc + c4 * 4);
            *(float4*)&xs[t][c4 * 4] = v;
        }
        __syncthreads();

        unsigned long long acc2[4][4] = {};
#pragma unroll
        for (int c4 = 0; c4 < 16; c4++) {
            ulonglong2 a0 = *(const ulonglong2*)&xs[tb + 0][c4 * 4];
            ulonglong2 a1 = *(const ulonglong2*)&xs[tb + 1][c4 * 4];
            ulonglong2 a2 = *(const ulonglong2*)&xs[tb + 2][c4 * 4];
            ulonglong2 a3 = *(const ulonglong2*)&xs[tb + 3][c4 * 4];
            ulonglong2 w0 = sW2[c4 * 64 + 0 * 16 + ff];
            ulonglong2 w1 = sW2[c4 * 64 + 1 * 16 + ff];
            ulonglong2 w2 = sW2[c4 * 64 + 2 * 16 + ff];
            ulonglong2 w3 = sW2[c4 * 64 + 3 * 16 + ff];
            fma2(acc2[0][0], a0.x, w0.x); fma2(acc2[0][0], a0.y, w0.y);
            fma2(acc2[0][1], a0.x, w1.x); fma2(acc2[0][1], a0.y, w1.y);
            fma2(acc2[0][2], a0.x, w2.x); fma2(acc2[0][2], a0.y, w2.y);
            fma2(acc2[0][3], a0.x, w3.x); fma2(acc2[0][3], a0.y, w3.y);
            fma2(acc2[1][0], a1.x, w0.x); fma2(acc2[1][0], a1.y, w0.y);
            fma2(acc2[1][1], a1.x, w1.x); fma2(acc2[1][1], a1.y, w1.y);
            fma2(acc2[1][2], a1.x, w2.x); fma2(acc2[1][2], a1.y, w2.y);
            fma2(acc2[1][3], a1.x, w3.x); fma2(acc2[1][3], a1.y, w3.y);
            fma2(acc2[2][0], a2.x, w0.x); fma2(acc2[2][0], a2.y, w0.y);
            fma2(acc2[2][1], a2.x, w1.x); fma2(acc2[2][1], a2.y, w1.y);
            fma2(acc2[2][2], a2.x, w2.x); fma2(acc2[2][2], a2.y, w2.y);
            fma2(acc2[2][3], a2.x, w3.x); fma2(acc2[2][3], a2.y, w3.y);
            fma2(acc2[3][0], a3.x, w0.x); fma2(acc2[3][0], a3.y, w0.y);
            fma2(acc2[3][1], a3.x, w1.x); fma2(acc2[3][1], a3.y, w1.y);
            fma2(acc2[3][2], a3.x, w2.x); fma2(acc2[3][2], a3.y, w2.y);
            fma2(acc2[3][3], a3.x, w3.x); fma2(acc2[3][3], a3.y, w3.y);
        }
        float acc[4][4];
#pragma unroll
        for (int i = 0; i < 4; i++)
#pragma unroll
            for (int j = 0; j < 4; j++) {
                float2 p = unpack2(acc2[i][j]);
                acc[i][j] = p.x + p.y;
            }

#pragma unroll
        for (int i = 0; i < 4; i++) {
            int token = token0 + tb + i;
            int pos = useH ? (token >> 7) : (token & 127);
            float k0 = elu1(acc[i][0] + bias4.x);
            float k1 = elu1(acc[i][1] + bias4.y);
            float k2 = elu1(acc[i][2] + bias4.z);
            float k3 = elu1(acc[i][3] + bias4.w);
            ksum[0] += k0; ksum[1] += k1; ksum[2] += k2; ksum[3] += k3;
            float2 cs0 = __ldg(&g_cs[pos * 16 + kid0]);
            float2 cs1 = __ldg(&g_cs[pos * 16 + kid1]);
            float4 kr;
            kr.x = k0 * cs0.x - k1 * cs0.y;
            kr.y = k0 * cs0.y + k1 * cs0.x;
            kr.z = k2 * cs1.x - k3 * cs1.y;
            kr.w = k2 * cs1.y + k3 * cs1.x;
            *(float4*)&ks[tb + i][f0] = kr;
        }
        __syncthreads();

        // kv accumulate (4x4 block, 16 tokens per thread via t-split)
#pragma unroll 4
        for (int t = q4 * 16; t < q4 * 16 + 16; t++) {
            ulonglong2 kk = *(const ulonglong2*)&ks[t][hd2 * 16 + d4];
            ulonglong2 vv = *(const ulonglong2*)&xs[t][hd2 * 16 + e4];
            float2 k01 = unpack2(kk.x), k23 = unpack2(kk.y);
            unsigned long long dk0 = pack2(k01.x, k01.x);
            unsigned long long dk1 = pack2(k01.y, k01.y);
            unsigned long long dk2 = pack2(k23.x, k23.x);
            unsigned long long dk3 = pack2(k23.y, k23.y);
            fma2(kvp[0][0], dk0, vv.x); fma2(kvp[0][1], dk0, vv.y);
            fma2(kvp[1][0], dk1, vv.x); fma2(kvp[1][1], dk1, vv.y);
            fma2(kvp[2][0], dk2, vv.x); fma2(kvp[2][1], dk2, vv.y);
            fma2(kvp[3][0], dk3, vv.x); fma2(kvp[3][1], dk3, vv.y);
        }
    }

    // block-level kv reduction over t-splits (deterministic), reuse ks
    __syncthreads();
    float* kred = &ks[0][0];   // 4096 floats
#pragma unroll
    for (int dj = 0; dj < 4; dj++) {
#pragma unroll
        for (int ep = 0; ep < 2; ep++) {
            float2 v = unpack2(kvp[dj][ep]);
            int entry0 = (hd2 * 16 + d4 + dj) * 16 + e4 + ep * 2;
            kred[entry0 * 4 + q4] = v.x;
            kred[(entry0 + 1) * 4 + q4] = v.y;
        }
    }
    __syncthreads();
    {
        float* pkv = g_part_kv + ((size_t)(b * PB + pb)) * 1024;
#pragma unroll
        for (int k = 0; k < 4; k++) {
            int entry = tid * 4 + k;
            float4 v = *(const float4*)&kred[entry * 4];
            pkv[entry] = (v.x + v.y) + (v.z + v.w);
        }
    }

    // ksum block reduction (deterministic), reuse ks
    __syncthreads();
    float* red = &ks[0][0];
#pragma unroll
    for (int j = 0; j < 4; j++) red[(f0 + j) * 16 + tt] = ksum[j];
    __syncthreads();
    if (tid < 64) {
        float s = 0.f;
#pragma unroll
        for (int g = 0; g < 16; g++) s += red[tid * 16 + g];
        g_part_ks[(size_t)(b * PB + pb) * 64 + tid] = s;
    }
}

// ---------------------------------------------------------------------------
__global__ __launch_bounds__(256) void reduce_pass() {
    const int b = blockIdx.x;
    const int tid = threadIdx.x;
    const float invN = 1.0f / (float)Nn;
    for (int e = tid; e < 1024; e += 256) {
        float s = 0.f;
        for (int p = 0; p < PB; p++) s += g_part_kv[(size_t)(b * PB + p) * 1024 + e];
        g_kvn[b * 1024 + e] = s * invN;
    }
    if (tid < 64) {
        float s = 0.f;
        for (int p = 0; p < PB; p++) s += g_part_ks[(size_t)(b * PB + p) * 64 + tid];
        g_kmean[b * 64 + tid] = s * invN;
    }
}

// ---------------------------------------------------------------------------
// q_pass smem (floats):
//  [0,4160)      Wi (4096) -> later lepe buf (64x65)
//  [4160,8512)   xs 64x68
//  [8512,12864)  qs 64x68  -> later attn buf (64x65)
//  [12864,13888) kv 1024
//  [13888,13952) km 64
//  [13952,14208) zsm 256
//  total 14208 floats = 56832 B   (4 blocks/SM)
// z computed via 4-lane head-group shuffles (no smem reduction).
// ---------------------------------------------------------------------------
__global__ __launch_bounds__(256, 4) void q_pass(const float* __restrict__ x,
                                                 const float* __restrict__ qkw,
                                                 const float* __restrict__ qkb,
                                                 const float* __restrict__ lw,
                                                 const float* __restrict__ lb,
                                                 float* __restrict__ out) {
    extern __shared__ float sm[];
    float4* sWi4 = (float4*)sm;
    const ulonglong2* sW2 = (const ulonglong2*)sm;
    float* slepe = sm;                                    // 64x65 after GEMM
    float (*xs)[68] = (float (*)[68])(sm + 4160);
    float (*qs)[68] = (float (*)[68])(sm + 8512);
    float* abuf = sm + 8512;                              // 64x65 after readout
    float* skv  = sm + 12864;
    float* skm  = sm + 13888;
    float* zsm  = sm + 13952;                             // [token][head] 64x4

    const int b = blockIdx.y;
    const int tile = blockIdx.x;
    const int tid = threadIdx.x;
    const int token0 = tile * TT;
    const float* xb = x + (size_t)b * Nn * Cc;

    for (int i = tid; i < 1024; i += 256) {
        int f = i >> 4, c4 = i & 15;
        float4 v = *(const float4*)(qkw + (size_t)f * 64 + c4 * 4);
        sWi4[c4 * 64 + (f & 3) * 16 + (f >> 2)] = v;
    }
    for (int i = tid; i < 1024; i += 256) skv[i] = g_kvn[b * 1024 + i];
    if (tid < 64) skm[tid] = g_kmean[b * 64 + tid];
    for (int i = tid; i < TT * 16; i += 256) {
        int t = i >> 4, c4 = i & 15;
        float4 v = *(const float4*)(xb + (size_t)(token0 + t) * Cc + c4 * 4);
        *(float4*)&xs[t][c4 * 4] = v;
    }
    __syncthreads();

    const int ff = tid & 15;
    const int tt = tid >> 4;
    const int f0 = ff * 4;
    const int tb = tt * 4;
    const int kid0 = (2 * ff) & 15, kid1 = (2 * ff + 1) & 15;
    const bool useH = (ff < 8);

    const float4 bias4 = *(const float4*)(qkb + f0);

    unsigned long long acc2[4][4] = {};
#pragma unroll
    for (int c4 = 0; c4 < 16; c4++) {
        ulonglong2 a0 = *(const ulonglong2*)&xs[tb + 0][c4 * 4];
        ulonglong2 a1 = *(const ulonglong2*)&xs[tb + 1][c4 * 4];
        ulonglong2 a2 = *(const ulonglong2*)&xs[tb + 2][c4 * 4];
        ulonglong2 a3 = *(const ulonglong2*)&xs[tb + 3][c4 * 4];
        ulonglong2 w0 = sW2[c4 * 64 + 0 * 16 + ff];
        ulonglong2 w1 = sW2[c4 * 64 + 1 * 16 + ff];
        ulonglong2 w2 = sW2[c4 * 64 + 2 * 16 + ff];
        ulonglong2 w3 = sW2[c4 * 64 + 3 * 16 + ff];
        fma2(acc2[0][0], a0.x, w0.x); fma2(acc2[0][0], a0.y, w0.y);
        fma2(acc2[0][1], a0.x, w1.x); fma2(acc2[0][1], a0.y, w1.y);
        fma2(acc2[0][2], a0.x, w2.x); fma2(acc2[0][2], a0.y, w2.y);
        fma2(acc2[0][3], a0.x, w3.x); fma2(acc2[0][3], a0.y, w3.y);
        fma2(acc2[1][0], a1.x, w0.x); fma2(acc2[1][0], a1.y, w0.y);
        fma2(acc2[1][1], a1.x, w1.x); fma2(acc2[1][1], a1.y, w1.y);
        fma2(acc2[1][2], a1.x, w2.x); fma2(acc2[1][2], a1.y, w2.y);
        fma2(acc2[1][3], a1.x, w3.x); fma2(acc2[1][3], a1.y, w3.y);
        fma2(acc2[2][0], a2.x, w0.x); fma2(acc2[2][0], a2.y, w0.y);
        fma2(acc2[2][1], a2.x, w1.x); fma2(acc2[2][1], a2.y, w1.y);
        fma2(acc2[2][2], a2.x, w2.x); fma2(acc2[2][2], a2.y, w2.y);
        fma2(acc2[2][3], a2.x, w3.x); fma2(acc2[2][3], a2.y, w3.y);
        fma2(acc2[3][0], a3.x, w0.x); fma2(acc2[3][0], a3.y, w0.y);
        fma2(acc2[3][1], a3.x, w1.x); fma2(acc2[3][1], a3.y, w1.y);
        fma2(acc2[3][2], a3.x, w2.x); fma2(acc2[3][2], a3.y, w2.y);
        fma2(acc2[3][3], a3.x, w3.x); fma2(acc2[3][3], a3.y, w3.y);
    }
    float acc[4][4];
#pragma unroll
    for (int i = 0; i < 4; i++)
#pragma unroll
        for (int j = 0; j < 4; j++) {
            float2 p = unpack2(acc2[i][j]);
            acc[i][j] = p.x + p.y;
        }

    const float4 kmv4 = *(const float4*)&skm[f0];

#pragma unroll
    for (int i = 0; i < 4; i++) {
        int token = token0 + tb + i;
        int pos = useH ? (token >> 7) : (token & 127);
        float q0 = elu1(acc[i][0] + bias4.x);
        float q1 = elu1(acc[i][1] + bias4.y);
        float q2 = elu1(acc[i][2] + bias4.z);
        float q3 = elu1(acc[i][3] + bias4.w);
        // z: sum over 16 d of this head = 4 lanes (adjacent) x 4 features
        float zp = q0 * kmv4.x + q1 * kmv4.y + q2 * kmv4.z + q3 * kmv4.w;
        zp += __shfl_xor_sync(0xffffffffu, zp, 1);
        zp += __shfl_xor_sync(0xffffffffu, zp, 2);
        if ((ff & 3) == 0) zsm[(tb + i) * 4 + (ff >> 2)] = 1.0f / (zp + 1e-6f);
        float2 cs0 = __ldg(&g_cs[pos * 16 + kid0]);
        float2 cs1 = __ldg(&g_cs[pos * 16 + kid1]);
        float4 qr;
        qr.x = q0 * cs0.x - q1 * cs0.y;
        qr.y = q0 * cs0.y + q1 * cs0.x;
        qr.z = q2 * cs1.x - q3 * cs1.y;
        qr.w = q2 * cs1.y + q3 * cs1.x;
        *(float4*)&qs[tb + i][f0] = qr;
    }
    __syncthreads();

    // readout: thread = (e 16, tg 2, hd 4, th 2); 16 tokens x 1 e each
    float areg[16];
    int rtbase;
    {
        int e  = tid & 15;
        int tg = (tid >> 4) & 1;
        int hd = (tid >> 5) & 3;
        int th = tid >> 7;
        rtbase = (th * 2 + tg) * 16;
        float kvc[16];
#pragma unroll
        for (int d = 0; d < 16; d++) kvc[d] = skv[hd * 256 + d * 16 + e];
        unsigned long long kv2[8];
#pragma unroll
        for (int p = 0; p < 8; p++) kv2[p] = pack2(kvc[2 * p], kvc[2 * p + 1]);
#pragma unroll
        for (int i = 0; i < 16; i++) {
            int t = rtbase + i;
            ulonglong2 q0 = *(const ulonglong2*)&qs[t][hd * 16 + 0];
            ulonglong2 q1 = *(const ulonglong2*)&qs[t][hd * 16 + 4];
            ulonglong2 q2 = *(const ulonglong2*)&qs[t][hd * 16 + 8];
            ulonglong2 q3 = *(const ulonglong2*)&qs[t][hd * 16 + 12];
            unsigned long long a2 = 0ull;
            fma2(a2, q0.x, kv2[0]); fma2(a2, q0.y, kv2[1]);
            fma2(a2, q1.x, kv2[2]); fma2(a2, q1.y, kv2[3]);
            fma2(a2, q2.x, kv2[4]); fma2(a2, q2.y, kv2[5]);
            fma2(a2, q3.x, kv2[6]); fma2(a2, q3.y, kv2[7]);
            float2 p = unpack2(a2);
            areg[i] = (p.x + p.y) * zsm[t * 4 + hd];
        }
    }
    __syncthreads();   // qs reads done; safe to overwrite qs (abuf) and Wi (slepe)
    {
        int e  = tid & 15;
        int hd = (tid >> 5) & 3;
#pragma unroll
        for (int i = 0; i < 16; i++) abuf[(rtbase + i) * 65 + hd * 16 + e] = areg[i];
    }

    // lepe: thread = (ch 64, tg 4), 16 consecutive w each, sliding window
    {
        int ch = tid & 63;
        int tg = tid >> 6;
        float w9[9];
#pragma unroll
        for (int k = 0; k < 9; k++) w9[k] = lw[ch * 9 + k];
        float bias = lb[ch];
        const int hh = token0 >> 7;
        const int ww0 = token0 & 127;
        const int wstart = ww0 + tg * 16;
        const bool hm = hh > 0, hp = hh < (Hh - 1);
        const float* rm = xb + ((size_t)(hh - 1) * Ww) * Cc + ch;
        const float* r0 = xb + ((size_t)hh * Ww) * Cc + ch;
        const float* rp = xb + ((size_t)(hh + 1) * Ww) * Cc + ch;

        float La, Lb2, Lc, Ma, Mb2, Mc, Ra, Rb2, Rc;
        {
            int gw = wstart - 1;
            if ((unsigned)gw < (unsigned)Ww) {
                La = hm ? rm[(size_t)gw * Cc] : 0.f;
                Lb2 = r0[(size_t)gw * Cc];
                Lc = hp ? rp[(size_t)gw * Cc] : 0.f;
            } else { La = Lb2 = Lc = 0.f; }
            gw = wstart;
            Ma = hm ? rm[(size_t)gw * Cc] : 0.f;
            Mb2 = r0[(size_t)gw * Cc];
            Mc = hp ? rp[(size_t)gw * Cc] : 0.f;
        }
#pragma unroll
        for (int j = 0; j < 16; j++) {
            int gw = wstart + j + 1;
            if ((unsigned)gw < (unsigned)Ww) {
                Ra = hm ? rm[(size_t)gw * Cc] : 0.f;
                Rb2 = r0[(size_t)gw * Cc];
                Rc = hp ? rp[(size_t)gw * Cc] : 0.f;
            } else { Ra = Rb2 = Rc = 0.f; }
            float s = bias;
            s = fmaf(w9[0], La, s);  s = fmaf(w9[1], Ma, s);  s = fmaf(w9[2], Ra, s);
            s = fmaf(w9[3], Lb2, s); s = fmaf(w9[4], Mb2, s); s = fmaf(w9[5], Rb2, s);
            s = fmaf(w9[6], Lc, s);  s = fmaf(w9[7], Mc, s);  s = fmaf(w9[8], Rc, s);
            slepe[(tg * 16 + j) * 65 + ch] = s;
            La = Ma; Lb2 = Mb2; Lc = Mc;
            Ma = Ra; Mb2 = Rb2; Mc = Rc;
        }
    }
    __syncthreads();

    // final NCHW write
    {
        int t = tid & 63, hg = tid >> 6;
        int token = token0 + t;
        float* ob = out + (size_t)b * Cc * Nn;
#pragma unroll
        for (int j = 0; j < 16; j++) {
            int ch = hg * 16 + j;
            ob[(size_t)ch * Nn + token] = abuf[t * 65 + ch] + slepe[t * 65 + ch];
        }
    }
}

// ---------------------------------------------------------------------------
extern "C" void kernel_launch(void* const* d_in, const int* in_sizes, int n_in,
                              void* d_out, int out_size) {
    const float* x   = (const float*)d_in[0];
    const float* qkw = (const float*)d_in[3];
    const float* qkb = (const float*)d_in[4];
    const float* lw  = (const float*)d_in[5];
    const float* lb  = (const float*)d_in[6];
    float* out = (float*)d_out;

    int B = in_sizes[0] / (Nn * Cc);
    if (B > BMAX) B = BMAX;

    const int SMEM_K = 12800 * sizeof(float);   // 51200
    const int SMEM_Q = 14208 * sizeof(float);   // 56832

    cudaFuncSetAttribute(k_pass, cudaFuncAttributeMaxDynamicSharedMemorySize, SMEM_K);
    cudaFuncSetAttribute(q_pass, cudaFuncAttributeMaxDynamicSharedMemorySize, SMEM_Q);

    init_tables<<<8, 256>>>();
    k_pass<<<dim3(PB, B), 256, SMEM_K>>>(x, qkw, qkb);
    reduce_pass<<<B, 256>>>();
    q_pass<<<dim3(TILES, B), 256, SMEM_Q>>>(x, qkw, qkb, lw, lb, out);
}

// round 10
// speedup vs baseline: 1.1605x; 1.1605x over previous
#include <cuda_runtime.h>
#include <cuda_bf16.h>
#include <math.h>
#include <stdint.h>

#define Hh 128
#define Ww 128
#define Nn (Hh*Ww)
#define Cc 64
#define TT 64
#define TILES (Nn/TT)
#define PB 64
#define BMAX 16

__device__ float g_part_kv[BMAX*PB*1024];
__device__ float g_part_ks[BMAX*PB*64];
__device__ float g_kvn[BMAX*1024];
__device__ float g_kmean[BMAX*64];
__device__ float2 g_cs[2048];

#define LN1E4_OVER16 0.57564627324851145f

__device__ __forceinline__ float elu1(float v) { return v > 0.f ? v + 1.f : __expf(v); }
__device__ __forceinline__ unsigned long long pack2(float lo, float hi) {
    unsigned long long r; asm("mov.b64 %0, {%1,%2};" : "=l"(r) : "f"(lo), "f"(hi)); return r;
}
__device__ __forceinline__ float2 unpack2(unsigned long long v) {
    float2 r; asm("mov.b64 {%0,%1}, %2;" : "=f"(r.x), "=f"(r.y) : "l"(v)); return r;
}
__device__ __forceinline__ void fma2(unsigned long long& d, unsigned long long a, unsigned long long b) {
    asm("fma.rn.f32x2 %0, %1, %2, %0;" : "+l"(d) : "l"(a), "l"(b));
}
__device__ __forceinline__ void bf_split(float a, float b, uint32_t& hi, uint32_t& lo) {
    __nv_bfloat162 h(__float2bfloat16(a), __float2bfloat16(b));
    hi = *(uint32_t*)&h;
    __nv_bfloat162 l(__float2bfloat16(a - __bfloat162float(h.x)),
                     __float2bfloat16(b - __bfloat162float(h.y)));
    lo = *(uint32_t*)&l;
}
__device__ __forceinline__ void mma_bf16(float* c, uint32_t a0, uint32_t a1, uint32_t a2,
                                         uint32_t a3, uint32_t b0, uint32_t b1) {
    asm volatile("mma.sync.aligned.m16n8k16.row.col.f32.bf16.bf16.f32 "
                 "{%0,%1,%2,%3}, {%4,%5,%6,%7}, {%8,%9}, {%0,%1,%2,%3};"
                 : "+f"(c[0]), "+f"(c[1]), "+f"(c[2]), "+f"(c[3])
                 : "r"(a0), "r"(a1), "r"(a2), "r"(a3), "r"(b0), "r"(b1));
}

__global__ void init_tables() {
    int idx = threadIdx.x + blockIdx.x * 256;
    if (idx < 2048) {
        int pos = idx >> 4, k = idx & 15;
        float theta = expf(-(float)k * LN1E4_OVER16);
        g_cs[idx] = make_float2(cosf((float)pos * theta), sinf((float)pos * theta));
    }
}

// ---------------------------------------------------------------------------
// k_pass (proven, unchanged): smem Wi 4096 | xs 64x68 | ks 64x68  (51200 B)
// ---------------------------------------------------------------------------
__global__ __launch_bounds__(256, 4) void k_pass(const float* __restrict__ x,
                                                 const float* __restrict__ qkw,
                                                 const float* __restrict__ qkb) {
    extern __shared__ float sm[];
    float4* sWi4 = (float4*)sm;
    const ulonglong2* sW2 = (const ulonglong2*)sm;
    float (*xs)[68] = (float (*)[68])(sm + 4096);
    float (*ks)[68] = (float (*)[68])(sm + 8448);

    const int b = blockIdx.y, pb = blockIdx.x, tid = threadIdx.x;

    for (int i = tid; i < 1024; i += 256) {
        int f = i >> 4, c4 = i & 15;
        float4 v = *(const float4*)(qkw + (size_t)(64 + f) * 64 + c4 * 4);
        sWi4[c4 * 64 + (f & 3) * 16 + (f >> 2)] = v;
    }

    const int ff = tid & 15, tt = tid >> 4;
    const int f0 = ff * 4, tb = tt * 4;
    const int kid0 = (2 * ff) & 15, kid1 = (2 * ff + 1) & 15;
    const bool useH = (ff < 8);
    const float4 bias4 = *(const float4*)(qkb + 64 + f0);

    float ksum[4] = {0.f, 0.f, 0.f, 0.f};
    const int e4 = (tid & 3) * 4, d4 = ((tid >> 2) & 3) * 4;
    const int q4 = (tid >> 4) & 3, hd2 = tid >> 6;
    unsigned long long kvp[4][2] = {};
    const float* xb = x + (size_t)b * Nn * Cc;

    for (int tile = pb; tile < TILES; tile += PB) {
        const int token0 = tile * TT;
        __syncthreads();
        for (int i = tid; i < TT * 16; i += 256) {
            int t = i >> 4, c4 = i & 15;
            *(float4*)&xs[t][c4 * 4] = *(const float4*)(xb + (size_t)(token0 + t) * Cc + c4 * 4);
        }
        __syncthreads();

        unsigned long long acc2[4][4] = {};
#pragma unroll
        for (int c4 = 0; c4 < 16; c4++) {
            ulonglong2 a[4];
#pragma unroll
            for (int i = 0; i < 4; i++) a[i] = *(const ulonglong2*)&xs[tb + i][c4 * 4];
#pragma unroll
            for (int j = 0; j < 4; j++) {
                ulonglong2 w = sW2[c4 * 64 + j * 16 + ff];
#pragma unroll
                for (int i = 0; i < 4; i++) { fma2(acc2[i][j], a[i].x, w.x); fma2(acc2[i][j], a[i].y, w.y); }
            }
        }
        float acc[4][4];
#pragma unroll
        for (int i = 0; i < 4; i++)
#pragma unroll
            for (int j = 0; j < 4; j++) { float2 p = unpack2(acc2[i][j]); acc[i][j] = p.x + p.y; }

#pragma unroll
        for (int i = 0; i < 4; i++) {
            int token = token0 + tb + i;
            int pos = useH ? (token >> 7) : (token & 127);
            float k0 = elu1(acc[i][0] + bias4.x), k1 = elu1(acc[i][1] + bias4.y);
            float k2 = elu1(acc[i][2] + bias4.z), k3 = elu1(acc[i][3] + bias4.w);
            ksum[0] += k0; ksum[1] += k1; ksum[2] += k2; ksum[3] += k3;
            float2 cs0 = __ldg(&g_cs[pos * 16 + kid0]);
            float2 cs1 = __ldg(&g_cs[pos * 16 + kid1]);
            float4 kr;
            kr.x = k0 * cs0.x - k1 * cs0.y; kr.y = k0 * cs0.y + k1 * cs0.x;
            kr.z = k2 * cs1.x - k3 * cs1.y; kr.w = k2 * cs1.y + k3 * cs1.x;
            *(float4*)&ks[tb + i][f0] = kr;
        }
        __syncthreads();

#pragma unroll 4
        for (int t = q4 * 16; t < q4 * 16 + 16; t++) {
            ulonglong2 kk = *(const ulonglong2*)&ks[t][hd2 * 16 + d4];
            ulonglong2 vv = *(const ulonglong2*)&xs[t][hd2 * 16 + e4];
            float2 k01 = unpack2(kk.x), k23 = unpack2(kk.y);
            unsigned long long dk[4] = {pack2(k01.x, k01.x), pack2(k01.y, k01.y),
                                        pack2(k23.x, k23.x), pack2(k23.y, k23.y)};
#pragma unroll
            for (int dj = 0; dj < 4; dj++) { fma2(kvp[dj][0], dk[dj], vv.x); fma2(kvp[dj][1], dk[dj], vv.y); }
        }
    }

    __syncthreads();
    float* kred = &ks[0][0];
#pragma unroll
    for (int dj = 0; dj < 4; dj++)
#pragma unroll
        for (int ep = 0; ep < 2; ep++) {
            float2 v = unpack2(kvp[dj][ep]);
            int entry0 = (hd2 * 16 + d4 + dj) * 16 + e4 + ep * 2;
            kred[entry0 * 4 + q4] = v.x;
            kred[(entry0 + 1) * 4 + q4] = v.y;
        }
    __syncthreads();
    {
        float* pkv = g_part_kv + ((size_t)(b * PB + pb)) * 1024;
#pragma unroll
        for (int k = 0; k < 4; k++) {
            float4 v = *(const float4*)&kred[(tid * 4 + k) * 4];
            pkv[tid * 4 + k] = (v.x + v.y) + (v.z + v.w);
        }
    }
    __syncthreads();
    float* red = &ks[0][0];
#pragma unroll
    for (int j = 0; j < 4; j++) red[(f0 + j) * 16 + tt] = ksum[j];
    __syncthreads();
    if (tid < 64) {
        float s = 0.f;
#pragma unroll
        for (int g = 0; g < 16; g++) s += red[tid * 16 + g];
        g_part_ks[(size_t)(b * PB + pb) * 64 + tid] = s;
    }
}

__global__ __launch_bounds__(256) void reduce_pass() {
    const int b = blockIdx.x, tid = threadIdx.x;
    const float invN = 1.0f / (float)Nn;
    for (int e = tid; e < 1024; e += 256) {
        float s = 0.f;
        for (int p = 0; p < PB; p++) s += g_part_kv[(size_t)(b * PB + p) * 1024 + e];
        g_kvn[b * 1024 + e] = s * invN;
    }
    if (tid < 64) {
        float s = 0.f;
        for (int p = 0; p < PB; p++) s += g_part_ks[(size_t)(b * PB + p) * 64 + tid];
        g_kmean[b * 64 + tid] = s * invN;
    }
}

// ===========================================================================
// q_pass_mma: warp-level HMMA (m16n8k16 bf16, hi/lo 3-term) for the q GEMM.
// smem layout (u32/float index):
//   u32:   A_HI 0 | A_LO 2304 | B_HI 4608 | B_LO 6912   (each 64 rows x 36 words)
//   float: qs 9216 (64x68) | skv 13568 | skm 14592 | skb 14656 | total 14720
//   overlays after GEMM: abuf = float 0 (64x65), slepe = float 4608 (64x65)
// ===========================================================================
#define UA_HI 0
#define UA_LO 2304
#define UB_HI 4608
#define UB_LO 6912
#define FQS   9216
#define FSKV  13568
#define FSKM  14592
#define FSKB  14656
#define SMEM_Q (14720 * 4)

__global__ __launch_bounds__(256, 3) void q_pass_mma(const float* __restrict__ x,
                                                     const float* __restrict__ qkw,
                                                     const float* __restrict__ qkb,
                                                     const float* __restrict__ lw,
                                                     const float* __restrict__ lb,
                                                     float* __restrict__ out) {
    extern __shared__ float sm[];
    uint32_t* su = (uint32_t*)sm;
    float (*qs)[68] = (float (*)[68])(sm + FQS);
    float* abuf  = sm;
    float* slepe = sm + 4608;
    float* skv   = sm + FSKV;
    float* skm   = sm + FSKM;
    float* skb   = sm + FSKB;

    const int b = blockIdx.y, tile = blockIdx.x, tid = threadIdx.x;
    const int wid = tid >> 5, lid = tid & 31;
    const int token0 = tile * TT;
    const float* xb = x + (size_t)b * Nn * Cc;

    // stage A (x tile) and B (q weights) as bf16 hi/lo, row stride 36 words
#pragma unroll
    for (int k = 0; k < 4; k++) {
        int idx = tid + k * 256;              // 0..1023 float4s
        int t = idx >> 4, c4 = idx & 15;
        float4 v = *(const float4*)(xb + (size_t)(token0 + t) * Cc + c4 * 4);
        uint32_t h0, l0, h1, l1;
        bf_split(v.x, v.y, h0, l0);
        bf_split(v.z, v.w, h1, l1);
        int o = t * 36 + c4 * 2;
        *(uint2*)&su[UA_HI + o] = make_uint2(h0, h1);
        *(uint2*)&su[UA_LO + o] = make_uint2(l0, l1);
        float4 w = *(const float4*)(qkw + (size_t)t * 64 + c4 * 4);
        bf_split(w.x, w.y, h0, l0);
        bf_split(w.z, w.w, h1, l1);
        *(uint2*)&su[UB_HI + o] = make_uint2(h0, h1);
        *(uint2*)&su[UB_LO + o] = make_uint2(l0, l1);
    }
    for (int i = tid; i < 1024; i += 256) skv[i] = g_kvn[b * 1024 + i];
    if (tid < 64) skm[tid] = g_kmean[b * 64 + tid];
    if (tid >= 64 && tid < 128) skb[tid - 64] = qkb[tid - 64];
    __syncthreads();

    // GEMM: warp wid -> m-tile (wid&3)*16, n-half (wid>>2)*32
    const int g = lid >> 2, t4 = lid & 3;
    const int wm = wid & 3, wn = wid >> 2;
    float acc[4][4] = {};
    const int arow0 = (wm * 16 + g) * 36;
    const int arow1 = arow0 + 8 * 36;
#pragma unroll
    for (int term = 0; term < 3; term++) {
        const int As = (term == 2) ? UA_LO : UA_HI;
        const int Bs = (term == 1) ? UB_LO : UB_HI;
#pragma unroll
        for (int kt = 0; kt < 4; kt++) {
            int wo = kt * 8 + t4;
            uint32_t a0 = su[As + arow0 + wo], a1 = su[As + arow1 + wo];
            uint32_t a2 = su[As + arow0 + wo + 4], a3 = su[As + arow1 + wo + 4];
#pragma unroll
            for (int nt = 0; nt < 4; nt++) {
                int brow = (wn * 32 + nt * 8 + g) * 36;
                mma_bf16(acc[nt], a0, a1, a2, a3, su[Bs + brow + wo], su[Bs + brow + wo + 4]);
            }
        }
    }

    // epilogue: bias + elu + z (fold) + rope -> qs
#pragma unroll
    for (int half = 0; half < 2; half++) {
        int r = wm * 16 + g + half * 8;
        int token = token0 + r;
        float q[8];
        float zp0 = 0.f, zp1 = 0.f;
#pragma unroll
        for (int nt = 0; nt < 4; nt++) {
            int n = wn * 32 + nt * 8 + t4 * 2;
            float q0 = elu1(acc[nt][half * 2 + 0] + skb[n]);
            float q1 = elu1(acc[nt][half * 2 + 1] + skb[n + 1]);
            float zc = q0 * skm[n] + q1 * skm[n + 1];
            if (nt < 2) zp0 += zc; else zp1 += zc;
            q[nt * 2] = q0; q[nt * 2 + 1] = q1;
        }
        zp0 += __shfl_xor_sync(0xffffffffu, zp0, 1);
        zp0 += __shfl_xor_sync(0xffffffffu, zp0, 2);
        zp1 += __shfl_xor_sync(0xffffffffu, zp1, 1);
        zp1 += __shfl_xor_sync(0xffffffffu, zp1, 2);
        float z0 = 1.0f / (zp0 + 1e-6f), z1 = 1.0f / (zp1 + 1e-6f);
        int pos = (wn == 0) ? (token >> 7) : (token & 127);
#pragma unroll
        for (int nt = 0; nt < 4; nt++) {
            int mg = nt * 4 + t4;   // pair index within wn half (0..15)
            float2 cs = __ldg(&g_cs[pos * 16 + mg]);
            float zz = (nt < 2) ? z0 : z1;
            float2 o;
            o.x = (q[2 * nt] * cs.x - q[2 * nt + 1] * cs.y) * zz;
            o.y = (q[2 * nt] * cs.y + q[2 * nt + 1] * cs.x) * zz;
            *(float2*)&qs[r][wn * 32 + nt * 8 + t4 * 2] = o;
        }
    }
    __syncthreads();

    // readout: thread = (e 16, tg 2, hd 4, th 2); 16 tokens x 1 e each (z folded)
    float areg[16];
    int rtbase;
    {
        int e = tid & 15, tg = (tid >> 4) & 1, hd = (tid >> 5) & 3, th = tid >> 7;
        rtbase = (th * 2 + tg) * 16;
        float kvc[16];
#pragma unroll
        for (int d = 0; d < 16; d++) kvc[d] = skv[hd * 256 + d * 16 + e];
        unsigned long long kv2[8];
#pragma unroll
        for (int p = 0; p < 8; p++) kv2[p] = pack2(kvc[2 * p], kvc[2 * p + 1]);
#pragma unroll
        for (int i = 0; i < 16; i++) {
            int t = rtbase + i;
            unsigned long long a2 = 0ull;
#pragma unroll
            for (int j = 0; j < 4; j++) {
                ulonglong2 qv = *(const ulonglong2*)&qs[t][hd * 16 + j * 4];
                fma2(a2, qv.x, kv2[2 * j]);
                fma2(a2, qv.y, kv2[2 * j + 1]);
            }
            float2 p = unpack2(a2);
            areg[i] = p.x + p.y;
        }
        // abuf overlays A mats (dead after GEMM) — no extra sync needed
        int e2 = tid & 15, hd2 = (tid >> 5) & 3;
#pragma unroll
        for (int i = 0; i < 16; i++) abuf[(rtbase + i) * 65 + hd2 * 16 + e2] = areg[i];
    }

    // lepe: thread = (ch 64, tg 4), 16 consecutive w each (slepe overlays B mats)
    {
        int ch = tid & 63, tg = tid >> 6;
        float w9[9];
#pragma unroll
        for (int k = 0; k < 9; k++) w9[k] = lw[ch * 9 + k];
        float biasl = lb[ch];
        const int hh = token0 >> 7;
        const int ww0 = token0 & 127;
        const int wstart = ww0 + tg * 16;
        const bool hm = hh > 0, hp = hh < (Hh - 1);
        const float* rm = xb + ((size_t)(hh - 1) * Ww) * Cc + ch;
        const float* r0 = xb + ((size_t)hh * Ww) * Cc + ch;
        const float* rp = xb + ((size_t)(hh + 1) * Ww) * Cc + ch;
        float La, Lb2, Lc, Ma, Mb2, Mc, Ra, Rb2, Rc;
        {
            int gw = wstart - 1;
            if ((unsigned)gw < (unsigned)Ww) {
                La = hm ? rm[(size_t)gw * Cc] : 0.f;
                Lb2 = r0[(size_t)gw * Cc];
                Lc = hp ? rp[(size_t)gw * Cc] : 0.f;
            } else { La = Lb2 = Lc = 0.f; }
            gw = wstart;
            Ma = hm ? rm[(size_t)gw * Cc] : 0.f;
            Mb2 = r0[(size_t)gw * Cc];
            Mc = hp ? rp[(size_t)gw * Cc] : 0.f;
        }
#pragma unroll
        for (int j = 0; j < 16; j++) {
            int gw = wstart + j + 1;
            if ((unsigned)gw < (unsigned)Ww) {
                Ra = hm ? rm[(size_t)gw * Cc] : 0.f;
                Rb2 = r0[(size_t)gw * Cc];
                Rc = hp ? rp[(size_t)gw * Cc] : 0.f;
            } else { Ra = Rb2 = Rc = 0.f; }
            float s = biasl;
            s = fmaf(w9[0], La, s);  s = fmaf(w9[1], Ma, s);  s = fmaf(w9[2], Ra, s);
            s = fmaf(w9[3], Lb2, s); s = fmaf(w9[4], Mb2, s); s = fmaf(w9[5], Rb2, s);
            s = fmaf(w9[6], Lc, s);  s = fmaf(w9[7], Mc, s);  s = fmaf(w9[8], Rc, s);
            slepe[(tg * 16 + j) * 65 + ch] = s;
            La = Ma; Lb2 = Mb2; Lc = Mc;
            Ma = Ra; Mb2 = Rb2; Mc = Rc;
        }
    }
    __syncthreads();

    // final NCHW write
    {
        int t = tid & 63, hg = tid >> 6;
        int token = token0 + t;
        float* ob = out + (size_t)b * Cc * Nn;
#pragma unroll
        for (int j = 0; j < 16; j++) {
            int ch = hg * 16 + j;
            ob[(size_t)ch * Nn + token] = abuf[t * 65 + ch] + slepe[t * 65 + ch];
        }
    }
}

// ---------------------------------------------------------------------------
extern "C" void kernel_launch(void* const* d_in, const int* in_sizes, int n_in,
                              void* d_out, int out_size) {
    const float* x   = (const float*)d_in[0];
    const float* qkw = (const float*)d_in[3];
    const float* qkb = (const float*)d_in[4];
    const float* lw  = (const float*)d_in[5];
    const float* lb  = (const float*)d_in[6];
    float* out = (float*)d_out;

    int B = in_sizes[0] / (Nn * Cc);
    if (B > BMAX) B = BMAX;

    const int SMEM_K = 12800 * sizeof(float);   // 51200
    cudaFuncSetAttribute(k_pass, cudaFuncAttributeMaxDynamicSharedMemorySize, SMEM_K);
    cudaFuncSetAttribute(q_pass_mma, cudaFuncAttributeMaxDynamicSharedMemorySize, SMEM_Q);

    init_tables<<<8, 256>>>();
    k_pass<<<dim3(PB, B), 256, SMEM_K>>>(x, qkw, qkb);
    reduce_pass<<<B, 256>>>();
    q_pass_mma<<<dim3(TILES, B), 256, SMEM_Q>>>(x, qkw, qkb, lw, lb, out);
}

// round 11
// speedup vs baseline: 1.2792x; 1.1023x over previous
#include <cuda_runtime.h>
#include <cuda_bf16.h>
#include <math.h>
#include <stdint.h>

#define Hh 128
#define Ww 128
#define Nn (Hh*Ww)
#define Cc 64
#define TT 64
#define TILES (Nn/TT)
#define PB 64
#define BMAX 16

__device__ float g_part_kv[BMAX*PB*1024];
__device__ float g_part_ks[BMAX*PB*64];
__device__ float g_kvn[BMAX*1024];
__device__ float g_kmean[BMAX*64];
__device__ float2 g_cs[2048];

#define LN1E4_OVER16 0.57564627324851145f

__device__ __forceinline__ float elu1(float v) { return v > 0.f ? v + 1.f : __expf(v); }
__device__ __forceinline__ unsigned long long pack2(float lo, float hi) {
    unsigned long long r; asm("mov.b64 %0, {%1,%2};" : "=l"(r) : "f"(lo), "f"(hi)); return r;
}
__device__ __forceinline__ float2 unpack2(unsigned long long v) {
    float2 r; asm("mov.b64 {%0,%1}, %2;" : "=f"(r.x), "=f"(r.y) : "l"(v)); return r;
}
__device__ __forceinline__ void fma2(unsigned long long& d, unsigned long long a, unsigned long long b) {
    asm("fma.rn.f32x2 %0, %1, %2, %0;" : "+l"(d) : "l"(a), "l"(b));
}
__device__ __forceinline__ void bf_split(float a, float b, uint32_t& hi, uint32_t& lo) {
    __nv_bfloat162 h(__float2bfloat16(a), __float2bfloat16(b));
    hi = *(uint32_t*)&h;
    __nv_bfloat162 l(__float2bfloat16(a - __bfloat162float(h.x)),
                     __float2bfloat16(b - __bfloat162float(h.y)));
    lo = *(uint32_t*)&l;
}
__device__ __forceinline__ void mma_bf16(float* c, uint32_t a0, uint32_t a1, uint32_t a2,
                                         uint32_t a3, uint32_t b0, uint32_t b1) {
    asm volatile("mma.sync.aligned.m16n8k16.row.col.f32.bf16.bf16.f32 "
                 "{%0,%1,%2,%3}, {%4,%5,%6,%7}, {%8,%9}, {%0,%1,%2,%3};"
                 : "+f"(c[0]), "+f"(c[1]), "+f"(c[2]), "+f"(c[3])
                 : "r"(a0), "r"(a1), "r"(a2), "r"(a3), "r"(b0), "r"(b1));
}

__global__ void init_tables() {
    int idx = threadIdx.x + blockIdx.x * 256;
    if (idx < 2048) {
        int pos = idx >> 4, k = idx & 15;
        float theta = expf(-(float)k * LN1E4_OVER16);
        g_cs[idx] = make_float2(cosf((float)pos * theta), sinf((float)pos * theta));
    }
}

// ===========================================================================
// k_pass_mma: HMMA GEMM + register epilogue + fp32 kv accumulation.
// smem (u32 idx): W_HI 0 | W_LO 2304 | A_HI 4608 | A_LO 6912 (9216 u32)
//   overlay: ks fp32 [64][68] at float 4608 (A region, dead after GEMM)
//   xs fp32 [64][68] at float 9216.  Total 13568 floats = 54272 B.
// ===========================================================================
#define KW_HI 0
#define KW_LO 2304
#define KA_HI 4608
#define KA_LO 6912
#define KKS   4608
#define KXS   9216
#define SMEM_K2 (13568 * 4)

__global__ __launch_bounds__(256, 4) void k_pass_mma(const float* __restrict__ x,
                                                     const float* __restrict__ qkw,
                                                     const float* __restrict__ qkb) {
    extern __shared__ float sm[];
    uint32_t* su = (uint32_t*)sm;
    float (*ks)[68] = (float (*)[68])(sm + KKS);
    float (*xs)[68] = (float (*)[68])(sm + KXS);

    const int b = blockIdx.y, pb = blockIdx.x, tid = threadIdx.x;
    const int wid = tid >> 5, lid = tid & 31;
    const int g = lid >> 2, t4 = lid & 3;
    const int wm = wid & 3, wn = wid >> 2;
    const float* xb = x + (size_t)b * Nn * Cc;

    // stage W (k weights, rows 64..127) bf16 hi/lo, stride 36 words
#pragma unroll
    for (int k = 0; k < 4; k++) {
        int idx = tid + k * 256;
        int f = idx >> 4, c4 = idx & 15;
        float4 w = *(const float4*)(qkw + (size_t)(64 + f) * 64 + c4 * 4);
        uint32_t h0, l0, h1, l1;
        bf_split(w.x, w.y, h0, l0);
        bf_split(w.z, w.w, h1, l1);
        int o = f * 36 + c4 * 2;
        *(uint2*)&su[KW_HI + o] = make_uint2(h0, h1);
        *(uint2*)&su[KW_LO + o] = make_uint2(l0, l1);
    }

    float ksum8[8] = {};
    const int e4 = (tid & 3) * 4, d4 = ((tid >> 2) & 3) * 4;
    const int q4 = (tid >> 4) & 3, hd2 = tid >> 6;
    unsigned long long kvp[4][2] = {};

    const int arow0 = (wm * 16 + g) * 36;
    const int arow1 = arow0 + 8 * 36;

    for (int tile = pb; tile < TILES; tile += PB) {
        const int token0 = tile * TT;
        __syncthreads();   // previous kv-loop readers of ks/xs done

        // stage x tile: fp32 (for v) + bf16 hi/lo (for MMA)
#pragma unroll
        for (int k = 0; k < 4; k++) {
            int idx = tid + k * 256;
            int t = idx >> 4, c4 = idx & 15;
            float4 v = *(const float4*)(xb + (size_t)(token0 + t) * Cc + c4 * 4);
            *(float4*)&xs[t][c4 * 4] = v;
            uint32_t h0, l0, h1, l1;
            bf_split(v.x, v.y, h0, l0);
            bf_split(v.z, v.w, h1, l1);
            int o = t * 36 + c4 * 2;
            *(uint2*)&su[KA_HI + o] = make_uint2(h0, h1);
            *(uint2*)&su[KA_LO + o] = make_uint2(l0, l1);
        }
        __syncthreads();

        // HMMA GEMM: warp (wm, wn) -> tokens wm*16..+15, features wn*32..+31
        float acc[4][4] = {};
#pragma unroll
        for (int term = 0; term < 3; term++) {
            const int As = (term == 2) ? KA_LO : KA_HI;
            const int Bs = (term == 1) ? KW_LO : KW_HI;
#pragma unroll
            for (int kt = 0; kt < 4; kt++) {
                int wo = kt * 8 + t4;
                uint32_t a0 = su[As + arow0 + wo], a1 = su[As + arow1 + wo];
                uint32_t a2 = su[As + arow0 + wo + 4], a3 = su[As + arow1 + wo + 4];
#pragma unroll
                for (int nt = 0; nt < 4; nt++) {
                    int brow = (wn * 32 + nt * 8 + g) * 36;
                    mma_bf16(acc[nt], a0, a1, a2, a3, su[Bs + brow + wo], su[Bs + brow + wo + 4]);
                }
            }
        }
        __syncthreads();   // all A reads done -> ks overlay safe

        // epilogue: bias+elu, ksum, rope -> ks
#pragma unroll
        for (int half = 0; half < 2; half++) {
            int r = wm * 16 + g + half * 8;
            int token = token0 + r;
            int pos = (wn == 0) ? (token >> 7) : (token & 127);
#pragma unroll
            for (int nt = 0; nt < 4; nt++) {
                int n = wn * 32 + nt * 8 + t4 * 2;
                float k0 = elu1(acc[nt][half * 2 + 0] + __ldg(qkb + 64 + n));
                float k1 = elu1(acc[nt][half * 2 + 1] + __ldg(qkb + 64 + n + 1));
                ksum8[nt * 2] += k0; ksum8[nt * 2 + 1] += k1;
                float2 cs = __ldg(&g_cs[pos * 16 + nt * 4 + t4]);
                float2 o;
                o.x = k0 * cs.x - k1 * cs.y;
                o.y = k0 * cs.y + k1 * cs.x;
                *(float2*)&ks[r][n] = o;
            }
        }
        __syncthreads();

        // kv accumulate (4x4 block, 16 tokens per thread via t-split)
#pragma unroll 4
        for (int t = q4 * 16; t < q4 * 16 + 16; t++) {
            ulonglong2 kk = *(const ulonglong2*)&ks[t][hd2 * 16 + d4];
            ulonglong2 vv = *(const ulonglong2*)&xs[t][hd2 * 16 + e4];
            float2 k01 = unpack2(kk.x), k23 = unpack2(kk.y);
            unsigned long long dk[4] = {pack2(k01.x, k01.x), pack2(k01.y, k01.y),
                                        pack2(k23.x, k23.x), pack2(k23.y, k23.y)};
#pragma unroll
            for (int dj = 0; dj < 4; dj++) { fma2(kvp[dj][0], dk[dj], vv.x); fma2(kvp[dj][1], dk[dj], vv.y); }
        }
    }

    // kv t-split reduction (deterministic), reuse ks region
    __syncthreads();
    float* kred = &ks[0][0];
#pragma unroll
    for (int dj = 0; dj < 4; dj++)
#pragma unroll
        for (int ep = 0; ep < 2; ep++) {
            float2 v = unpack2(kvp[dj][ep]);
            int entry0 = (hd2 * 16 + d4 + dj) * 16 + e4 + ep * 2;
            kred[entry0 * 4 + q4] = v.x;
            kred[(entry0 + 1) * 4 + q4] = v.y;
        }
    __syncthreads();
    {
        float* pkv = g_part_kv + ((size_t)(b * PB + pb)) * 1024;
#pragma unroll
        for (int k = 0; k < 4; k++) {
            float4 v = *(const float4*)&kred[(tid * 4 + k) * 4];
            pkv[tid * 4 + k] = (v.x + v.y) + (v.z + v.w);
        }
    }

    // ksum reduction: 32 contributors (wm x g) per column
    __syncthreads();
    float* red = &ks[0][0];   // 2048 floats
#pragma unroll
    for (int j = 0; j < 8; j++) {
        int c = wn * 32 + (j >> 1) * 8 + t4 * 2 + (j & 1);
        red[c * 32 + wm * 8 + g] = ksum8[j];
    }
    __syncthreads();
    if (tid < 64) {
        float s = 0.f;
#pragma unroll
        for (int i = 0; i < 32; i++) s += red[tid * 32 + i];
        g_part_ks[(size_t)(b * PB + pb) * 64 + tid] = s;
    }
}

__global__ __launch_bounds__(256) void reduce_pass() {
    const int b = blockIdx.x, tid = threadIdx.x;
    const float invN = 1.0f / (float)Nn;
    for (int e = tid; e < 1024; e += 256) {
        float s = 0.f;
        for (int p = 0; p < PB; p++) s += g_part_kv[(size_t)(b * PB + p) * 1024 + e];
        g_kvn[b * 1024 + e] = s * invN;
    }
    if (tid < 64) {
        float s = 0.f;
        for (int p = 0; p < PB; p++) s += g_part_ks[(size_t)(b * PB + p) * 64 + tid];
        g_kmean[b * 64 + tid] = s * invN;
    }
}

// ===========================================================================
// q_pass_mma (unchanged from R10, 98.8 us)
// ===========================================================================
#define UA_HI 0
#define UA_LO 2304
#define UB_HI 4608
#define UB_LO 6912
#define FQS   9216
#define FSKV  13568
#define FSKM  14592
#define FSKB  14656
#define SMEM_Q (14720 * 4)

__global__ __launch_bounds__(256, 3) void q_pass_mma(const float* __restrict__ x,
                                                     const float* __restrict__ qkw,
                                                     const float* __restrict__ qkb,
                                                     const float* __restrict__ lw,
                                                     const float* __restrict__ lb,
                                                     float* __restrict__ out) {
    extern __shared__ float sm[];
    uint32_t* su = (uint32_t*)sm;
    float (*qs)[68] = (float (*)[68])(sm + FQS);
    float* abuf  = sm;
    float* slepe = sm + 4608;
    float* skv   = sm + FSKV;
    float* skm   = sm + FSKM;
    float* skb   = sm + FSKB;

    const int b = blockIdx.y, tile = blockIdx.x, tid = threadIdx.x;
    const int wid = tid >> 5, lid = tid & 31;
    const int token0 = tile * TT;
    const float* xb = x + (size_t)b * Nn * Cc;

#pragma unroll
    for (int k = 0; k < 4; k++) {
        int idx = tid + k * 256;
        int t = idx >> 4, c4 = idx & 15;
        float4 v = *(const float4*)(xb + (size_t)(token0 + t) * Cc + c4 * 4);
        uint32_t h0, l0, h1, l1;
        bf_split(v.x, v.y, h0, l0);
        bf_split(v.z, v.w, h1, l1);
        int o = t * 36 + c4 * 2;
        *(uint2*)&su[UA_HI + o] = make_uint2(h0, h1);
        *(uint2*)&su[UA_LO + o] = make_uint2(l0, l1);
        float4 w = *(const float4*)(qkw + (size_t)t * 64 + c4 * 4);
        bf_split(w.x, w.y, h0, l0);
        bf_split(w.z, w.w, h1, l1);
        *(uint2*)&su[UB_HI + o] = make_uint2(h0, h1);
        *(uint2*)&su[UB_LO + o] = make_uint2(l0, l1);
    }
    for (int i = tid; i < 1024; i += 256) skv[i] = g_kvn[b * 1024 + i];
    if (tid < 64) skm[tid] = g_kmean[b * 64 + tid];
    if (tid >= 64 && tid < 128) skb[tid - 64] = qkb[tid - 64];
    __syncthreads();

    const int g = lid >> 2, t4 = lid & 3;
    const int wm = wid & 3, wn = wid >> 2;
    float acc[4][4] = {};
    const int arow0 = (wm * 16 + g) * 36;
    const int arow1 = arow0 + 8 * 36;
#pragma unroll
    for (int term = 0; term < 3; term++) {
        const int As = (term == 2) ? UA_LO : UA_HI;
        const int Bs = (term == 1) ? UB_LO : UB_HI;
#pragma unroll
        for (int kt = 0; kt < 4; kt++) {
            int wo = kt * 8 + t4;
            uint32_t a0 = su[As + arow0 + wo], a1 = su[As + arow1 + wo];
            uint32_t a2 = su[As + arow0 + wo + 4], a3 = su[As + arow1 + wo + 4];
#pragma unroll
            for (int nt = 0; nt < 4; nt++) {
                int brow = (wn * 32 + nt * 8 + g) * 36;
                mma_bf16(acc[nt], a0, a1, a2, a3, su[Bs + brow + wo], su[Bs + brow + wo + 4]);
            }
        }
    }

#pragma unroll
    for (int half = 0; half < 2; half++) {
        int r = wm * 16 + g + half * 8;
        int token = token0 + r;
        float q[8];
        float zp0 = 0.f, zp1 = 0.f;
#pragma unroll
        for (int nt = 0; nt < 4; nt++) {
            int n = wn * 32 + nt * 8 + t4 * 2;
            float q0 = elu1(acc[nt][half * 2 + 0] + skb[n]);
            float q1 = elu1(acc[nt][half * 2 + 1] + skb[n + 1]);
            float zc = q0 * skm[n] + q1 * skm[n + 1];
            if (nt < 2) zp0 += zc; else zp1 += zc;
            q[nt * 2] = q0; q[nt * 2 + 1] = q1;
        }
        zp0 += __shfl_xor_sync(0xffffffffu, zp0, 1);
        zp0 += __shfl_xor_sync(0xffffffffu, zp0, 2);
        zp1 += __shfl_xor_sync(0xffffffffu, zp1, 1);
        zp1 += __shfl_xor_sync(0xffffffffu, zp1, 2);
        float z0 = 1.0f / (zp0 + 1e-6f), z1 = 1.0f / (zp1 + 1e-6f);
        int pos = (wn == 0) ? (token >> 7) : (token & 127);
#pragma unroll
        for (int nt = 0; nt < 4; nt++) {
            int mg = nt * 4 + t4;
            float2 cs = __ldg(&g_cs[pos * 16 + mg]);
            float zz = (nt < 2) ? z0 : z1;
            float2 o;
            o.x = (q[2 * nt] * cs.x - q[2 * nt + 1] * cs.y) * zz;
            o.y = (q[2 * nt] * cs.y + q[2 * nt + 1] * cs.x) * zz;
            *(float2*)&qs[r][wn * 32 + nt * 8 + t4 * 2] = o;
        }
    }
    __syncthreads();

    float areg[16];
    int rtbase;
    {
        int e = tid & 15, tg = (tid >> 4) & 1, hd = (tid >> 5) & 3, th = tid >> 7;
        rtbase = (th * 2 + tg) * 16;
        float kvc[16];
#pragma unroll
        for (int d = 0; d < 16; d++) kvc[d] = skv[hd * 256 + d * 16 + e];
        unsigned long long kv2[8];
#pragma unroll
        for (int p = 0; p < 8; p++) kv2[p] = pack2(kvc[2 * p], kvc[2 * p + 1]);
#pragma unroll
        for (int i = 0; i < 16; i++) {
            int t = rtbase + i;
            unsigned long long a2 = 0ull;
#pragma unroll
            for (int j = 0; j < 4; j++) {
                ulonglong2 qv = *(const ulonglong2*)&qs[t][hd * 16 + j * 4];
                fma2(a2, qv.x, kv2[2 * j]);
                fma2(a2, qv.y, kv2[2 * j + 1]);
            }
            float2 p = unpack2(a2);
            areg[i] = p.x + p.y;
        }
        int e2 = tid & 15, hd2 = (tid >> 5) & 3;
#pragma unroll
        for (int i = 0; i < 16; i++) abuf[(rtbase + i) * 65 + hd2 * 16 + e2] = areg[i];
    }

    {
        int ch = tid & 63, tg = tid >> 6;
        float w9[9];
#pragma unroll
        for (int k = 0; k < 9; k++) w9[k] = lw[ch * 9 + k];
        float biasl = lb[ch];
        const int hh = token0 >> 7;
        const int ww0 = token0 & 127;
        const int wstart = ww0 + tg * 16;
        const bool hm = hh > 0, hp = hh < (Hh - 1);
        const float* rm = xb + ((size_t)(hh - 1) * Ww) * Cc + ch;
        const float* r0 = xb + ((size_t)hh * Ww) * Cc + ch;
        const float* rp = xb + ((size_t)(hh + 1) * Ww) * Cc + ch;
        float La, Lb2, Lc, Ma, Mb2, Mc, Ra, Rb2, Rc;
        {
            int gw = wstart - 1;
            if ((unsigned)gw < (unsigned)Ww) {
                La = hm ? rm[(size_t)gw * Cc] : 0.f;
                Lb2 = r0[(size_t)gw * Cc];
                Lc = hp ? rp[(size_t)gw * Cc] : 0.f;
            } else { La = Lb2 = Lc = 0.f; }
            gw = wstart;
            Ma = hm ? rm[(size_t)gw * Cc] : 0.f;
            Mb2 = r0[(size_t)gw * Cc];
            Mc = hp ? rp[(size_t)gw * Cc] : 0.f;
        }
#pragma unroll
        for (int j = 0; j < 16; j++) {
            int gw = wstart + j + 1;
            if ((unsigned)gw < (unsigned)Ww) {
                Ra = hm ? rm[(size_t)gw * Cc] : 0.f;
                Rb2 = r0[(size_t)gw * Cc];
                Rc = hp ? rp[(size_t)gw * Cc] : 0.f;
            } else { Ra = Rb2 = Rc = 0.f; }
            float s = biasl;
            s = fmaf(w9[0], La, s);  s = fmaf(w9[1], Ma, s);  s = fmaf(w9[2], Ra, s);
            s = fmaf(w9[3], Lb2, s); s = fmaf(w9[4], Mb2, s); s = fmaf(w9[5], Rb2, s);
            s = fmaf(w9[6], Lc, s);  s = fmaf(w9[7], Mc, s);  s = fmaf(w9[8], Rc, s);
            slepe[(tg * 16 + j) * 65 + ch] = s;
            La = Ma; Lb2 = Mb2; Lc = Mc;
            Ma = Ra; Mb2 = Rb2; Mc = Rc;
        }
    }
    __syncthreads();

    {
        int t = tid & 63, hg = tid >> 6;
        int token = token0 + t;
        float* ob = out + (size_t)b * Cc * Nn;
#pragma unroll
        for (int j = 0; j < 16; j++) {
            int ch = hg * 16 + j;
            ob[(size_t)ch * Nn + token] = abuf[t * 65 + ch] + slepe[t * 65 + ch];
        }
    }
}

// ---------------------------------------------------------------------------
extern "C" void kernel_launch(void* const* d_in, const int* in_sizes, int n_in,
                              void* d_out, int out_size) {
    const float* x   = (const float*)d_in[0];
    const float* qkw = (const float*)d_in[3];
    const float* qkb = (const float*)d_in[4];
    const float* lw  = (const float*)d_in[5];
    const float* lb  = (const float*)d_in[6];
    float* out = (float*)d_out;

    int B = in_sizes[0] / (Nn * Cc);
    if (B > BMAX) B = BMAX;

    cudaFuncSetAttribute(k_pass_mma, cudaFuncAttributeMaxDynamicSharedMemorySize, SMEM_K2);
    cudaFuncSetAttribute(q_pass_mma, cudaFuncAttributeMaxDynamicSharedMemorySize, SMEM_Q);

    init_tables<<<8, 256>>>();
    k_pass_mma<<<dim3(PB, B), 256, SMEM_K2>>>(x, qkw, qkb);
    reduce_pass<<<B, 256>>>();
    q_pass_mma<<<dim3(TILES, B), 256, SMEM_Q>>>(x, qkw, qkb, lw, lb, out);
}

// round 13
// speedup vs baseline: 1.3828x; 1.0810x over previous
#include <cuda_runtime.h>
#include <cuda_bf16.h>
#include <math.h>
#include <stdint.h>

#define Hh 128
#define Ww 128
#define Nn (Hh*Ww)
#define Cc 64
#define TT 64
#define TILES (Nn/TT)
#define PB 64
#define BMAX 16

__device__ float g_part_kv[BMAX*PB*1024];
__device__ float g_part_ks[BMAX*PB*64];
__device__ float g_kvn[BMAX*1024];
__device__ float g_kmean[BMAX*64];
__device__ float2 g_cs[2048];

#define LN1E4_OVER16 0.57564627324851145f

__device__ __forceinline__ float elu1(float v) { return v > 0.f ? v + 1.f : __expf(v); }
__device__ __forceinline__ unsigned long long pack2(float lo, float hi) {
    unsigned long long r; asm("mov.b64 %0, {%1,%2};" : "=l"(r) : "f"(lo), "f"(hi)); return r;
}
__device__ __forceinline__ float2 unpack2(unsigned long long v) {
    float2 r; asm("mov.b64 {%0,%1}, %2;" : "=f"(r.x), "=f"(r.y) : "l"(v)); return r;
}
__device__ __forceinline__ void fma2(unsigned long long& d, unsigned long long a, unsigned long long b) {
    asm("fma.rn.f32x2 %0, %1, %2, %0;" : "+l"(d) : "l"(a), "l"(b));
}
__device__ __forceinline__ void bf_split(float a, float b, uint32_t& hi, uint32_t& lo) {
    __nv_bfloat162 h(__float2bfloat16(a), __float2bfloat16(b));
    hi = *(uint32_t*)&h;
    __nv_bfloat162 l(__float2bfloat16(a - __bfloat162float(h.x)),
                     __float2bfloat16(b - __bfloat162float(h.y)));
    lo = *(uint32_t*)&l;
}
__device__ __forceinline__ void mma_bf16(float* c, uint32_t a0, uint32_t a1, uint32_t a2,
                                         uint32_t a3, uint32_t b0, uint32_t b1) {
    asm volatile("mma.sync.aligned.m16n8k16.row.col.f32.bf16.bf16.f32 "
                 "{%0,%1,%2,%3}, {%4,%5,%6,%7}, {%8,%9}, {%0,%1,%2,%3};"
                 : "+f"(c[0]), "+f"(c[1]), "+f"(c[2]), "+f"(c[3])
                 : "r"(a0), "r"(a1), "r"(a2), "r"(a3), "r"(b0), "r"(b1));
}

__global__ void init_tables() {
    int idx = threadIdx.x + blockIdx.x * 256;
    if (idx < 2048) {
        int pos = idx >> 4, k = idx & 15;
        float theta = expf(-(float)k * LN1E4_OVER16);
        g_cs[idx] = make_float2(cosf((float)pos * theta), sinf((float)pos * theta));
    }
}

// ===========================================================================
// k_pass_mma (unchanged from R11, proven 192.6us pipeline)
// ===========================================================================
#define KW_HI 0
#define KW_LO 2304
#define KA_HI 4608
#define KA_LO 6912
#define KKS   4608
#define KXS   9216
#define SMEM_K2 (13568 * 4)

__global__ __launch_bounds__(256, 4) void k_pass_mma(const float* __restrict__ x,
                                                     const float* __restrict__ qkw,
                                                     const float* __restrict__ qkb) {
    extern __shared__ float sm[];
    uint32_t* su = (uint32_t*)sm;
    float (*ks)[68] = (float (*)[68])(sm + KKS);
    float (*xs)[68] = (float (*)[68])(sm + KXS);

    const int b = blockIdx.y, pb = blockIdx.x, tid = threadIdx.x;
    const int wid = tid >> 5, lid = tid & 31;
    const int g = lid >> 2, t4 = lid & 3;
    const int wm = wid & 3, wn = wid >> 2;
    const float* xb = x + (size_t)b * Nn * Cc;

#pragma unroll
    for (int k = 0; k < 4; k++) {
        int idx = tid + k * 256;
        int f = idx >> 4, c4 = idx & 15;
        float4 w = *(const float4*)(qkw + (size_t)(64 + f) * 64 + c4 * 4);
        uint32_t h0, l0, h1, l1;
        bf_split(w.x, w.y, h0, l0);
        bf_split(w.z, w.w, h1, l1);
        int o = f * 36 + c4 * 2;
        *(uint2*)&su[KW_HI + o] = make_uint2(h0, h1);
        *(uint2*)&su[KW_LO + o] = make_uint2(l0, l1);
    }

    float ksum8[8] = {};
    const int e4 = (tid & 3) * 4, d4 = ((tid >> 2) & 3) * 4;
    const int q4 = (tid >> 4) & 3, hd2 = tid >> 6;
    unsigned long long kvp[4][2] = {};
    const int arow0 = (wm * 16 + g) * 36;
    const int arow1 = arow0 + 8 * 36;

    for (int tile = pb; tile < TILES; tile += PB) {
        const int token0 = tile * TT;
        __syncthreads();
#pragma unroll
        for (int k = 0; k < 4; k++) {
            int idx = tid + k * 256;
            int t = idx >> 4, c4 = idx & 15;
            float4 v = *(const float4*)(xb + (size_t)(token0 + t) * Cc + c4 * 4);
            *(float4*)&xs[t][c4 * 4] = v;
            uint32_t h0, l0, h1, l1;
            bf_split(v.x, v.y, h0, l0);
            bf_split(v.z, v.w, h1, l1);
            int o = t * 36 + c4 * 2;
            *(uint2*)&su[KA_HI + o] = make_uint2(h0, h1);
            *(uint2*)&su[KA_LO + o] = make_uint2(l0, l1);
        }
        __syncthreads();

        float acc[4][4] = {};
#pragma unroll
        for (int term = 0; term < 3; term++) {
            const int As = (term == 2) ? KA_LO : KA_HI;
            const int Bs = (term == 1) ? KW_LO : KW_HI;
#pragma unroll
            for (int kt = 0; kt < 4; kt++) {
                int wo = kt * 8 + t4;
                uint32_t a0 = su[As + arow0 + wo], a1 = su[As + arow1 + wo];
                uint32_t a2 = su[As + arow0 + wo + 4], a3 = su[As + arow1 + wo + 4];
#pragma unroll
                for (int nt = 0; nt < 4; nt++) {
                    int brow = (wn * 32 + nt * 8 + g) * 36;
                    mma_bf16(acc[nt], a0, a1, a2, a3, su[Bs + brow + wo], su[Bs + brow + wo + 4]);
                }
            }
        }
        __syncthreads();

#pragma unroll
        for (int half = 0; half < 2; half++) {
            int r = wm * 16 + g + half * 8;
            int token = token0 + r;
            int pos = (wn == 0) ? (token >> 7) : (token & 127);
#pragma unroll
            for (int nt = 0; nt < 4; nt++) {
                int n = wn * 32 + nt * 8 + t4 * 2;
                float k0 = elu1(acc[nt][half * 2 + 0] + __ldg(qkb + 64 + n));
                float k1 = elu1(acc[nt][half * 2 + 1] + __ldg(qkb + 64 + n + 1));
                ksum8[nt * 2] += k0; ksum8[nt * 2 + 1] += k1;
                float2 cs = __ldg(&g_cs[pos * 16 + nt * 4 + t4]);
                float2 o;
                o.x = k0 * cs.x - k1 * cs.y;
                o.y = k0 * cs.y + k1 * cs.x;
                *(float2*)&ks[r][n] = o;
            }
        }
        __syncthreads();

#pragma unroll 4
        for (int t = q4 * 16; t < q4 * 16 + 16; t++) {
            ulonglong2 kk = *(const ulonglong2*)&ks[t][hd2 * 16 + d4];
            ulonglong2 vv = *(const ulonglong2*)&xs[t][hd2 * 16 + e4];
            float2 k01 = unpack2(kk.x), k23 = unpack2(kk.y);
            unsigned long long dk[4] = {pack2(k01.x, k01.x), pack2(k01.y, k01.y),
                                        pack2(k23.x, k23.x), pack2(k23.y, k23.y)};
#pragma unroll
            for (int dj = 0; dj < 4; dj++) { fma2(kvp[dj][0], dk[dj], vv.x); fma2(kvp[dj][1], dk[dj], vv.y); }
        }
    }

    __syncthreads();
    float* kred = &ks[0][0];
#pragma unroll
    for (int dj = 0; dj < 4; dj++)
#pragma unroll
        for (int ep = 0; ep < 2; ep++) {
            float2 v = unpack2(kvp[dj][ep]);
            int entry0 = (hd2 * 16 + d4 + dj) * 16 + e4 + ep * 2;
            kred[entry0 * 4 + q4] = v.x;
            kred[(entry0 + 1) * 4 + q4] = v.y;
        }
    __syncthreads();
    {
        float* pkv = g_part_kv + ((size_t)(b * PB + pb)) * 1024;
#pragma unroll
        for (int k = 0; k < 4; k++) {
            float4 v = *(const float4*)&kred[(tid * 4 + k) * 4];
            pkv[tid * 4 + k] = (v.x + v.y) + (v.z + v.w);
        }
    }
    __syncthreads();
    float* red = &ks[0][0];
#pragma unroll
    for (int j = 0; j < 8; j++) {
        int c = wn * 32 + (j >> 1) * 8 + t4 * 2 + (j & 1);
        red[c * 32 + wm * 8 + g] = ksum8[j];
    }
    __syncthreads();
    if (tid < 64) {
        float s = 0.f;
#pragma unroll
        for (int i = 0; i < 32; i++) s += red[tid * 32 + i];
        g_part_ks[(size_t)(b * PB + pb) * 64 + tid] = s;
    }
}

__global__ __launch_bounds__(256) void reduce_pass() {
    const int b = blockIdx.x, tid = threadIdx.x;
    const float invN = 1.0f / (float)Nn;
    for (int e = tid; e < 1024; e += 256) {
        float s = 0.f;
        for (int p = 0; p < PB; p++) s += g_part_kv[(size_t)(b * PB + p) * 1024 + e];
        g_kvn[b * 1024 + e] = s * invN;
    }
    if (tid < 64) {
        float s = 0.f;
        for (int p = 0; p < PB; p++) s += g_part_ks[(size_t)(b * PB + p) * 64 + tid];
        g_kmean[b * 64 + tid] = s * invN;
    }
}

// ===========================================================================
// q_pass_mma v2: GEMM1 (HMMA) -> register epilogue -> GEMM2 (HMMA fragment
// reuse). Overlay row stride 66 (even) so float2 stores stay 8B-aligned.
// smem floats: su A/B hi/lo [0,9216) | skv 9216 | skm 10240 | skb 10304 | 10368
// overlays after GEMM1: abuf float 0 (64x66), slepe float 4224 (64x66)
// ===========================================================================
#define UA_HI 0
#define UA_LO 2304
#define UB_HI 4608
#define UB_LO 6912
#define FSKV  9216
#define FSKM  10240
#define FSKB  10304
#define SMEM_Q (10368 * 4)
#define AST 66

__global__ __launch_bounds__(256, 4) void q_pass_mma(const float* __restrict__ x,
                                                     const float* __restrict__ qkw,
                                                     const float* __restrict__ qkb,
                                                     const float* __restrict__ lw,
                                                     const float* __restrict__ lb,
                                                     float* __restrict__ out) {
    extern __shared__ float sm[];
    uint32_t* su = (uint32_t*)sm;
    float* abuf  = sm;
    float* slepe = sm + 64 * AST;
    float* skv   = sm + FSKV;
    float* skm   = sm + FSKM;
    float* skb   = sm + FSKB;

    const int b = blockIdx.y, tile = blockIdx.x, tid = threadIdx.x;
    const int wid = tid >> 5, lid = tid & 31;
    const int token0 = tile * TT;
    const float* xb = x + (size_t)b * Nn * Cc;

#pragma unroll
    for (int k = 0; k < 4; k++) {
        int idx = tid + k * 256;
        int t = idx >> 4, c4 = idx & 15;
        float4 v = *(const float4*)(xb + (size_t)(token0 + t) * Cc + c4 * 4);
        uint32_t h0, l0, h1, l1;
        bf_split(v.x, v.y, h0, l0);
        bf_split(v.z, v.w, h1, l1);
        int o = t * 36 + c4 * 2;
        *(uint2*)&su[UA_HI + o] = make_uint2(h0, h1);
        *(uint2*)&su[UA_LO + o] = make_uint2(l0, l1);
        float4 w = *(const float4*)(qkw + (size_t)t * 64 + c4 * 4);
        bf_split(w.x, w.y, h0, l0);
        bf_split(w.z, w.w, h1, l1);
        *(uint2*)&su[UB_HI + o] = make_uint2(h0, h1);
        *(uint2*)&su[UB_LO + o] = make_uint2(l0, l1);
    }
    for (int i = tid; i < 1024; i += 256) skv[i] = g_kvn[b * 1024 + i];
    if (tid < 64) skm[tid] = g_kmean[b * 64 + tid];
    if (tid >= 64 && tid < 128) skb[tid - 64] = qkb[tid - 64];
    __syncthreads();

    const int g = lid >> 2, t4 = lid & 3;
    const int wm = wid & 3, wn = wid >> 2;

    // GEMM1: x @ Wq^T (hi/lo 3-term)
    float acc[4][4] = {};
    const int arow0 = (wm * 16 + g) * 36;
    const int arow1 = arow0 + 8 * 36;
#pragma unroll
    for (int term = 0; term < 3; term++) {
        const int As = (term == 2) ? UA_LO : UA_HI;
        const int Bs = (term == 1) ? UB_LO : UB_HI;
#pragma unroll
        for (int kt = 0; kt < 4; kt++) {
            int wo = kt * 8 + t4;
            uint32_t a0 = su[As + arow0 + wo], a1 = su[As + arow1 + wo];
            uint32_t a2 = su[As + arow0 + wo + 4], a3 = su[As + arow1 + wo + 4];
#pragma unroll
            for (int nt = 0; nt < 4; nt++) {
                int brow = (wn * 32 + nt * 8 + g) * 36;
                mma_bf16(acc[nt], a0, a1, a2, a3, su[Bs + brow + wo], su[Bs + brow + wo + 4]);
            }
        }
    }

    // epilogue: elu, z (t4-lane shuffles), rope, z-fold -> A-fragments for GEMM2
    uint32_t afh[2][4], afl[2][4];
#pragma unroll
    for (int half = 0; half < 2; half++) {
        int r = wm * 16 + g + half * 8;
        int token = token0 + r;
        float q[8];
        float zp0 = 0.f, zp1 = 0.f;
#pragma unroll
        for (int nt = 0; nt < 4; nt++) {
            int n = wn * 32 + nt * 8 + t4 * 2;
            float q0 = elu1(acc[nt][half * 2 + 0] + skb[n]);
            float q1 = elu1(acc[nt][half * 2 + 1] + skb[n + 1]);
            float zc = q0 * skm[n] + q1 * skm[n + 1];
            if (nt < 2) zp0 += zc; else zp1 += zc;
            q[nt * 2] = q0; q[nt * 2 + 1] = q1;
        }
        zp0 += __shfl_xor_sync(0xffffffffu, zp0, 1);
        zp0 += __shfl_xor_sync(0xffffffffu, zp0, 2);
        zp1 += __shfl_xor_sync(0xffffffffu, zp1, 1);
        zp1 += __shfl_xor_sync(0xffffffffu, zp1, 2);
        float z0 = 1.0f / (zp0 + 1e-6f), z1 = 1.0f / (zp1 + 1e-6f);
        int pos = (wn == 0) ? (token >> 7) : (token & 127);
#pragma unroll
        for (int nt = 0; nt < 4; nt++) {
            float2 cs = __ldg(&g_cs[pos * 16 + nt * 4 + t4]);
            float zz = (nt < 2) ? z0 : z1;
            float ox = (q[2 * nt] * cs.x - q[2 * nt + 1] * cs.y) * zz;
            float oy = (q[2 * nt] * cs.y + q[2 * nt + 1] * cs.x) * zz;
            int hh2 = nt >> 1, slot = (nt & 1) * 2 + half;
            bf_split(ox, oy, afh[hh2][slot], afl[hh2][slot]);
        }
    }
    __syncthreads();   // all su reads done -> abuf/slepe overlays safe

    // GEMM2: out = q_rope_z @ kv  (per warp: heads 2wn, 2wn+1; all 16 e)
#pragma unroll
    for (int hh2 = 0; hh2 < 2; hh2++) {
        int head = wn * 2 + hh2;
        const float* kvh = skv + head * 256 + g;
#pragma unroll
        for (int nh = 0; nh < 2; nh++) {
            const float* kb = kvh + nh * 8;
            float f00 = kb[(2 * t4) * 16],     f01 = kb[(2 * t4 + 1) * 16];
            float f10 = kb[(2 * t4 + 8) * 16], f11 = kb[(2 * t4 + 9) * 16];
            uint32_t bh0, bl0, bh1, bl1;
            bf_split(f00, f01, bh0, bl0);
            bf_split(f10, f11, bh1, bl1);
            float c[4] = {0.f, 0.f, 0.f, 0.f};
            mma_bf16(c, afh[hh2][0], afh[hh2][1], afh[hh2][2], afh[hh2][3], bh0, bh1);
            mma_bf16(c, afh[hh2][0], afh[hh2][1], afh[hh2][2], afh[hh2][3], bl0, bl1);
            mma_bf16(c, afl[hh2][0], afl[hh2][1], afl[hh2][2], afl[hh2][3], bh0, bh1);
            int col = head * 16 + nh * 8 + 2 * t4;
            int r0 = wm * 16 + g;
            *(float2*)&abuf[r0 * AST + col]       = make_float2(c[0], c[1]);
            *(float2*)&abuf[(r0 + 8) * AST + col] = make_float2(c[2], c[3]);
        }
    }

    // lepe: thread = (ch 64, tg 4), 16 consecutive w each
    {
        int ch = tid & 63, tg = tid >> 6;
        float w9[9];
#pragma unroll
        for (int k = 0; k < 9; k++) w9[k] = lw[ch * 9 + k];
        float biasl = lb[ch];
        const int hh = token0 >> 7;
        const int ww0 = token0 & 127;
        const int wstart = ww0 + tg * 16;
        const bool hm = hh > 0, hp = hh < (Hh - 1);
        const float* rm = xb + ((size_t)(hh - 1) * Ww) * Cc + ch;
        const float* r0p = xb + ((size_t)hh * Ww) * Cc + ch;
        const float* rp = xb + ((size_t)(hh + 1) * Ww) * Cc + ch;
        float La, Lb2, Lc, Ma, Mb2, Mc, Ra, Rb2, Rc;
        {
            int gw = wstart - 1;
            if ((unsigned)gw < (unsigned)Ww) {
                La = hm ? rm[(size_t)gw * Cc] : 0.f;
                Lb2 = r0p[(size_t)gw * Cc];
                Lc = hp ? rp[(size_t)gw * Cc] : 0.f;
            } else { La = Lb2 = Lc = 0.f; }
            gw = wstart;
            Ma = hm ? rm[(size_t)gw * Cc] : 0.f;
            Mb2 = r0p[(size_t)gw * Cc];
            Mc = hp ? rp[(size_t)gw * Cc] : 0.f;
        }
#pragma unroll
        for (int j = 0; j < 16; j++) {
            int gw = wstart + j + 1;
            if ((unsigned)gw < (unsigned)Ww) {
                Ra = hm ? rm[(size_t)gw * Cc] : 0.f;
                Rb2 = r0p[(size_t)gw * Cc];
                Rc = hp ? rp[(size_t)gw * Cc] : 0.f;
            } else { Ra = Rb2 = Rc = 0.f; }
            float s = biasl;
            s = fmaf(w9[0], La, s);  s = fmaf(w9[1], Ma, s);  s = fmaf(w9[2], Ra, s);
            s = fmaf(w9[3], Lb2, s); s = fmaf(w9[4], Mb2, s); s = fmaf(w9[5], Rb2, s);
            s = fmaf(w9[6], Lc, s);  s = fmaf(w9[7], Mc, s);  s = fmaf(w9[8], Rc, s);
            slepe[(tg * 16 + j) * AST + ch] = s;
            La = Ma; Lb2 = Mb2; Lc = Mc;
            Ma = Ra; Mb2 = Rb2; Mc = Rc;
        }
    }
    __syncthreads();

    // final NCHW write
    {
        int t = tid & 63, hg = tid >> 6;
        int token = token0 + t;
        float* ob = out + (size_t)b * Cc * Nn;
#pragma unroll
        for (int j = 0; j < 16; j++) {
            int ch = hg * 16 + j;
            ob[(size_t)ch * Nn + token] = abuf[t * AST + ch] + slepe[t * AST + ch];
        }
    }
}

// ---------------------------------------------------------------------------
extern "C" void kernel_launch(void* const* d_in, const int* in_sizes, int n_in,
                              void* d_out, int out_size) {
    const float* x   = (const float*)d_in[0];
    const float* qkw = (const float*)d_in[3];
    const float* qkb = (const float*)d_in[4];
    const float* lw  = (const float*)d_in[5];
    const float* lb  = (const float*)d_in[6];
    float* out = (float*)d_out;

    int B = in_sizes[0] / (Nn * Cc);
    if (B > BMAX) B = BMAX;

    cudaFuncSetAttribute(k_pass_mma, cudaFuncAttributeMaxDynamicSharedMemorySize, SMEM_K2);
    cudaFuncSetAttribute(q_pass_mma, cudaFuncAttributeMaxDynamicSharedMemorySize, SMEM_Q);

    init_tables<<<8, 256>>>();
    k_pass_mma<<<dim3(PB, B), 256, SMEM_K2>>>(x, qkw, qkb);
    reduce_pass<<<B, 256>>>();
    q_pass_mma<<<dim3(TILES, B), 256, SMEM_Q>>>(x, qkw, qkb, lw, lb, out);
}